// round 6
// baseline (speedup 1.0000x reference)
#include <cuda_runtime.h>
#include <cuda_bf16.h>
#include <math.h>

#define KS    11
#define HALO  5
#define IMG   512
#define TW    256          // tile width (outputs)
#define TH    32           // tile height (outputs)
#define WROWS (TH + KS - 1)   // 42 rows loaded per column
#define PCOLS 320          // columns loaded per block: [x0-32, x0+288), 128B aligned
#define TSTR  321          // smem row stride; 321 mod 32 = 1 -> conflict-free across rows
#define NTHR  320          // 10 warps

__device__ float g_w[KS];

// Pre-kernel: normalized 1D Gaussian from sigma (separable 2D kernel).
__global__ void gb_weights_kernel(const float* __restrict__ sigma) {
    if (threadIdx.x == 0) {
        float s = fabsf(sigma[0]) + 1e-6f;
        float inv2s2 = 1.0f / (2.0f * s * s);
        float w[KS];
        float sum = 0.0f;
        #pragma unroll
        for (int i = 0; i < KS; i++) {
            float r = (float)i - (float)(KS - 1) * 0.5f;
            w[i] = expf(-(r * r) * inv2s2);
            sum += w[i];
        }
        float inv = 1.0f / sum;
        #pragma unroll
        for (int i = 0; i < KS; i++) g_w[i] = w[i] * inv;
    }
}

__device__ __forceinline__ int reflect_idx(int i) {
    i = (i < 0) ? -i : i;
    return (i > IMG - 1) ? 2 * (IMG - 1) - i : i;
}

__global__ void __launch_bounds__(NTHR, 2)
gb_blur_kernel(const float* __restrict__ x, float* __restrict__ out) {
    __shared__ float tmp[TH * TSTR];   // 32 x 321 floats = 41.1 KB

    const int tid   = threadIdx.x;
    const int plane = blockIdx.z;
    const int x0    = blockIdx.x * TW;
    const int y0    = blockIdx.y * TH;

    const float* __restrict__ base = x + (size_t)plane * (IMG * IMG);

    float w[KS];
    #pragma unroll
    for (int k = 0; k < KS; k++) w[k] = __ldg(&g_w[k]);

    // ---------------- P1: vertical pass, global -> smem ----------------
    // One column per thread, 320 columns [x0-32, x0+288). Warp lanes read
    // consecutive, 128B-aligned addresses (1 wavefront per LDG). Full
    // register preload of the 42-row window -> 42 independent LDGs in flight.
    {
        const int cx = reflect_idx(x0 - 32 + tid);
        const float* __restrict__ col = base + cx;

        float raw[WROWS];
        #pragma unroll
        for (int rr = 0; rr < WROWS; rr++) {
            int y = y0 - HALO + rr;
            y = (y < 0) ? -y : ((y > IMG - 1) ? 2 * (IMG - 1) - y : y);
            raw[rr] = __ldg(col + y * IMG);
        }

        #pragma unroll
        for (int r = 0; r < TH; r++) {
            float acc = 0.0f;
            #pragma unroll
            for (int k = 0; k < KS; k++)
                acc = fmaf(raw[r + k], w[k], acc);
            tmp[r * TSTR + tid] = acc;
        }
    }
    __syncthreads();

    // ---------------- P2: horizontal pass, smem -> registers ----------------
    // Warp wp (0..7) owns output columns [x0+32*wp, x0+32*wp+32); lane = row.
    // Window reads: addr = lane*321 + const -> banks = lane + const,
    // conflict-free. Preload the whole 42-wide window into registers, then
    // sync so tmp can be reused as transpose scratch.
    const int wp   = tid >> 5;
    const int lane = tid & 31;

    float win[TW / 8 / 4 * 0 + 42];   // 42 window values
    if (wp < 8) {
        const float* __restrict__ trow = tmp + lane * TSTR + wp * 32 + 27;
        #pragma unroll
        for (int i = 0; i < 42; i++) win[i] = trow[i];
    }
    __syncthreads();   // all window reads done; tmp is dead

    // ---------------- P3: compute + warp transpose + coalesced store ----------
    if (wp < 8) {
        float* patch = tmp + wp * (32 * 33);   // per-warp 32x33 patch (reuses tmp)

        #pragma unroll
        for (int j = 0; j < 32; j++) {
            float acc = 0.0f;
            #pragma unroll
            for (int k = 0; k < KS; k++)
                acc = fmaf(win[j + k], w[k], acc);
            patch[lane * 33 + j] = acc;        // banks = lane + j : conflict-free
        }
        __syncwarp();

        float* __restrict__ obase =
            out + (size_t)plane * (IMG * IMG) + (size_t)y0 * IMG + x0 + wp * 32 + lane;
        #pragma unroll
        for (int rr = 0; rr < 32; rr++) {
            // transposed read: banks = 33*rr + lane -> conflict-free
            obase[rr * IMG] = patch[rr * 33 + lane];   // lanes consecutive: coalesced
        }
    }
}

extern "C" void kernel_launch(void* const* d_in, const int* in_sizes, int n_in,
                              void* d_out, int out_size) {
    const float* x     = (const float*)d_in[0];   // (16, 64, 512, 512) fp32
    const float* sigma = (const float*)d_in[1];   // (1,) fp32
    float* out = (float*)d_out;

    gb_weights_kernel<<<1, 32>>>(sigma);

    dim3 grid(IMG / TW, IMG / TH, 16 * 64);       // (2, 16, 1024)
    gb_blur_kernel<<<grid, NTHR>>>(x, out);
}